// round 5
// baseline (speedup 1.0000x reference)
#include <cuda_runtime.h>
#include <cstdint>
#include <cstddef>

// FPS: B=8, N=131072, NPOINT=1024 -> out [8,1024,3] fp32.
// 128 flat CTAs (16 per batch) x 512 threads, all co-resident (grid < #SM).
// Each CTA owns 8192 points = 8 f32x2 pairs/thread, ALL in registers.
// Per step: packed-f32x2 update (no LDS), REDUX argmax (max dist, min idx),
// block reduce -> publish 32B partial to a global slot (payload store +
// release-store of {z,tag}) -> every warp acquire-polls the 16 slots of its
// batch and reduces them; next centroid lands in registers. Slots are
// double-buffered by step parity (2-deep pipeline => no overwrite hazard).

#define NB       8
#define NPTS     131072
#define NSAMP    1024
#define NCTA     16                 // CTAs per batch
#define TPB      512
#define PPB      (NPTS / NCTA)      // 8192 points per CTA
#define PAIRS    (PPB / 2)          // 4096 pairs per CTA
#define REGJ     (PAIRS / TPB)      // 8 pairs per thread (all in regs)
#define NPT      (2 * REGJ)         // 16 points per thread
#define NWARPS   (TPB / 32)         // 16

struct __align__(32) GSlot {
    uint4 p0;                   // v, i, x, y
    unsigned long long zt;      // (z_bits << 32) | tag
    unsigned long long pad;
};
__device__ GSlot g_slots[2][NB][NCTA];   // zero-initialized; tag 0 never matches

struct __align__(16) Red { unsigned v, i; float x, y, z; unsigned pad[3]; };

struct Smem {
    Red warpred[NWARPS];
    unsigned long long xs2[PAIRS];   // packed {x_even, x_odd} per pair
    unsigned long long ys2[PAIRS];
    unsigned long long zs2[PAIRS];
};

// ---------- helpers ----------
__device__ __forceinline__ unsigned long long packf2(float lo, float hi) {
    unsigned long long r;
    asm("mov.b64 %0, {%1, %2};" : "=l"(r) : "f"(lo), "f"(hi));
    return r;
}
__device__ __forceinline__ void unpackf2(unsigned long long v, float& lo, float& hi) {
    asm("mov.b64 {%0, %1}, %2;" : "=f"(lo), "=f"(hi) : "l"(v));
}
__device__ __forceinline__ unsigned long long addx2(unsigned long long a,
                                                    unsigned long long b) {
    unsigned long long r;
    asm("add.rn.f32x2 %0, %1, %2;" : "=l"(r) : "l"(a), "l"(b));
    return r;
}
__device__ __forceinline__ unsigned long long mulx2(unsigned long long a,
                                                    unsigned long long b) {
    unsigned long long r;
    asm("mul.rn.f32x2 %0, %1, %2;" : "=l"(r) : "l"(a), "l"(b));
    return r;
}
__device__ __forceinline__ unsigned long long fmx2(unsigned long long a,
                                                   unsigned long long b,
                                                   unsigned long long c) {
    unsigned long long r;
    asm("fma.rn.f32x2 %0, %1, %2, %3;" : "=l"(r) : "l"(a), "l"(b), "l"(c));
    return r;
}
__device__ __forceinline__ void stg_v4(GSlot* s, unsigned a, unsigned b,
                                       unsigned c, unsigned d) {
    asm volatile("st.global.v4.b32 [%0], {%1,%2,%3,%4};"
                 :: "l"(&s->p0), "r"(a), "r"(b), "r"(c), "r"(d) : "memory");
}
__device__ __forceinline__ void stg_release_u64(GSlot* s, unsigned long long v) {
    asm volatile("st.release.gpu.global.b64 [%0], %1;"
                 :: "l"(&s->zt), "l"(v) : "memory");
}
__device__ __forceinline__ unsigned long long ldg_acquire_u64(const GSlot* s) {
    unsigned long long r;
    asm volatile("ld.acquire.gpu.global.b64 %0, [%1];"
                 : "=l"(r) : "l"(&s->zt) : "memory");
    return r;
}
__device__ __forceinline__ uint4 ldg_v4(const GSlot* s) {
    uint4 r;
    asm volatile("ld.global.v4.b32 {%0,%1,%2,%3}, [%4];"
                 : "=r"(r.x), "=r"(r.y), "=r"(r.z), "=r"(r.w)
                 : "l"(&s->p0) : "memory");
    return r;
}

__global__ void __launch_bounds__(TPB, 1)
fps_kernel(const float* __restrict__ xyz, float* __restrict__ out) {
    extern __shared__ __align__(16) unsigned char smem_raw[];
    Smem* s = reinterpret_cast<Smem*>(smem_raw);

    const int      tid   = threadIdx.x;
    const unsigned lane  = tid & 31;
    const unsigned warp  = (unsigned)tid >> 5;
    const int      bid   = blockIdx.x;
    const int      batch = bid >> 4;          // / NCTA
    const unsigned cid   = (unsigned)bid & 15u;

    const float* __restrict__ base = xyz + (size_t)batch * NPTS * 3;
    const unsigned pbase = cid * PPB;

    // ---- load ALL pairs into registers; mirror into SMEM for candidate fetch
    unsigned long long X[REGJ], Y[REGJ], Z[REGJ];
#pragma unroll
    for (int j = 0; j < REGJ; ++j) {
        unsigned P = (unsigned)j * TPB + (unsigned)tid;
        const float2* p = reinterpret_cast<const float2*>(
            base + (size_t)(pbase + 2u * P) * 3);
        float2 a = p[0];  // x0 y0
        float2 b = p[1];  // z0 x1
        float2 c = p[2];  // y1 z1
        X[j] = packf2(a.x, b.y);
        Y[j] = packf2(a.y, c.x);
        Z[j] = packf2(b.x, c.y);
        s->xs2[P] = X[j];
        s->ys2[P] = Y[j];
        s->zs2[P] = Z[j];
    }

    float m[NPT];
#pragma unroll
    for (int k = 0; k < NPT; ++k) m[k] = __int_as_float(0x7f800000);  // +inf

    // initial centroid = point 0 of this batch
    float cx = __ldg(base + 0);
    float cy = __ldg(base + 1);
    float cz = __ldg(base + 2);
    if (cid == 0 && tid == 0) {
        float* o = out + (size_t)batch * NSAMP * 3;
        o[0] = cx; o[1] = cy; o[2] = cz;
    }
    __syncthreads();   // smem mirror ready

    for (int t = 1; t < NSAMP; ++t) {
        const unsigned long long ncx = packf2(-cx, -cx);
        const unsigned long long ncy = packf2(-cy, -cy);
        const unsigned long long ncz = packf2(-cz, -cz);

        // ---- update mindist (registers only); two independent max chains ----
        float bmA = -1.0f, bmB = -1.0f;
#pragma unroll
        for (int j = 0; j < REGJ; ++j) {
            unsigned long long dx = addx2(X[j], ncx);
            unsigned long long dy = addx2(Y[j], ncy);
            unsigned long long dz = addx2(Z[j], ncz);
            unsigned long long dd = mulx2(dx, dx);
            dd = fmx2(dy, dy, dd);
            dd = fmx2(dz, dz, dd);
            float d0, d1; unpackf2(dd, d0, d1);
            float m0 = fminf(m[2 * j],     d0);
            float m1 = fminf(m[2 * j + 1], d1);
            m[2 * j] = m0; m[2 * j + 1] = m1;
            bmA = fmaxf(bmA, m0);
            bmB = fmaxf(bmB, m1);
        }
        const float bm = fmaxf(bmA, bmB);

        // ---- smallest k with m[k]==bm ----
        int kk = 0;
#pragma unroll
        for (int k = NPT - 1; k >= 0; --k)
            if (m[k] == bm) kk = k;

        unsigned Pw   = (unsigned)(kk >> 1) * TPB + (unsigned)tid;
        unsigned gidx = pbase + 2u * Pw + (unsigned)(kk & 1);
        float a0, a1, b0, b1, c0, c1;
        unpackf2(s->xs2[Pw], a0, a1);
        unpackf2(s->ys2[Pw], b0, b1);
        unpackf2(s->zs2[Pw], c0, c1);
        float candx = (kk & 1) ? a1 : a0;
        float candy = (kk & 1) ? b1 : b0;
        float candz = (kk & 1) ? c1 : c0;

        // ---- warp reduce: max dist bits, then min index among maxima ----
        unsigned vb = __float_as_uint(bm);   // d>=0: int order == float order
        unsigned wv = __reduce_max_sync(0xffffffffu, vb);
        unsigned cd = (vb == wv) ? gidx : 0xffffffffu;
        unsigned wi = __reduce_min_sync(0xffffffffu, cd);
        if (cd == wi) {                      // unique winner lane stores
            *reinterpret_cast<uint4*>(&s->warpred[warp]) =
                make_uint4(wv, wi, __float_as_uint(candx), __float_as_uint(candy));
            s->warpred[warp].z = candz;
        }
        __syncthreads();

        const int par = t & 1;
        GSlot* bslots = &g_slots[par][batch][0];

        // ---- warp 0: block reduce over 16 warp partials, publish to L2 ----
        if (warp == 0) {
            unsigned v = 0, i = 0xffffffffu, xb = 0, yb = 0, zb = 0;
            if (lane < NWARPS) {
                uint4 w = *reinterpret_cast<const uint4*>(&s->warpred[lane]);
                v = w.x; i = w.y; xb = w.z; yb = w.w;
                zb = __float_as_uint(s->warpred[lane].z);
            }
            unsigned bv = __reduce_max_sync(0xffffffffu, v);
            unsigned bc = (v == bv) ? i : 0xffffffffu;
            unsigned bi = __reduce_min_sync(0xffffffffu, bc);
            unsigned msk = __ballot_sync(0xffffffffu, bc == bi);
            int L = __ffs(msk) - 1;
            xb = __shfl_sync(0xffffffffu, xb, L);
            yb = __shfl_sync(0xffffffffu, yb, L);
            zb = __shfl_sync(0xffffffffu, zb, L);
            if (lane == 0) {
                GSlot* my = bslots + cid;
                stg_v4(my, bv, bi, xb, yb);
                stg_release_u64(my, ((unsigned long long)zb << 32) | (unsigned)t);
            }
        }

        // ---- EVERY warp polls the 16 slots of its batch, reduces locally ----
        {
            unsigned v = 0, i = 0xffffffffu, xb = 0, yb = 0, zb = 0;
            if (lane < NCTA) {
                const GSlot* sl = bslots + lane;
                unsigned long long zt;
                do { zt = ldg_acquire_u64(sl); } while ((unsigned)zt != (unsigned)t);
                zb = (unsigned)(zt >> 32);
                uint4 p = ldg_v4(sl);        // ordered after the acquire
                v = p.x; i = p.y; xb = p.z; yb = p.w;
            }
            unsigned cv = __reduce_max_sync(0xffffffffu, v);
            unsigned cc = (v == cv) ? i : 0xffffffffu;
            unsigned ci = __reduce_min_sync(0xffffffffu, cc);
            unsigned msk = __ballot_sync(0xffffffffu, cc == ci);
            int W = __ffs(msk) - 1;
            cx = __uint_as_float(__shfl_sync(0xffffffffu, xb, W));
            cy = __uint_as_float(__shfl_sync(0xffffffffu, yb, W));
            cz = __uint_as_float(__shfl_sync(0xffffffffu, zb, W));
            if (cid == 0 && tid == 0) {
                float* o = out + ((size_t)batch * NSAMP + (size_t)t) * 3;
                o[0] = cx; o[1] = cy; o[2] = cz;
            }
        }
        // warpred hazard: each warp rewrites only its own entry after its own
        // warp stage; warp0 reads it right after the block-wide __syncthreads.
        // g_slots hazard: parity double-buffer + "writer can be at most one
        // step ahead" pipeline argument => no overwrite before all reads.
    }
}

extern "C" void kernel_launch(void* const* d_in, const int* in_sizes, int n_in,
                              void* d_out, int out_size) {
    (void)in_sizes; (void)n_in; (void)out_size;
    const float* xyz = (const float*)d_in[0];
    float* out = (float*)d_out;

    cudaFuncSetAttribute(fps_kernel,
                         cudaFuncAttributeMaxDynamicSharedMemorySize,
                         (int)sizeof(Smem));

    fps_kernel<<<NB * NCTA, TPB, sizeof(Smem)>>>(xyz, out);
}

// round 6
// speedup vs baseline: 3.0476x; 3.0476x over previous
#include <cuda_runtime.h>
#include <cstdint>
#include <cstddef>

// FPS: B=8, N=131072, NPOINT=1024 -> out [8,1024,3] fp32.
// 8 clusters (one per batch) x 8 CTAs x 1024 threads (R3 skeleton, 2x warps).
// Each CTA owns 16384 points = 8 f32x2 pairs/thread; pairs 0..3 in REGISTERS,
// pairs 4..7 streamed from SMEM (full packed mirror kept in SMEM for the
// once-per-step candidate coordinate fetch). Argmax = (max dist, min index)
// via REDUX; winner coords ride warpred -> DSMEM slots; one barrier.cluster
// per step; every warp reduces the 8 slots -> next centroid in registers.

#define NB       8
#define NPTS     131072
#define NSAMP    1024
#define CSIZE    8
#define TPB      1024
#define PPB      (NPTS / CSIZE)    // 16384 points per CTA
#define PAIRS    (PPB / 2)         // 8192 pairs per CTA
#define TOTJ     (PAIRS / TPB)     // 8 pairs per thread
#define REGJ     4                 // pairs per thread held in registers
#define NPT      (2 * TOTJ)        // 16 points per thread
#define NWARPS   (TPB / 32)        // 32

struct __align__(16) Red { unsigned v, i; float x, y, z; unsigned pad[3]; };  // 32B

struct Smem {
    Red warpred[NWARPS];
    Red slots[2][CSIZE];
    unsigned long long xs2[PAIRS];   // packed {x_even, x_odd} per pair
    unsigned long long ys2[PAIRS];
    unsigned long long zs2[PAIRS];
};

// ---------- asm helpers ----------
__device__ __forceinline__ unsigned ctarank() {
    unsigned r; asm("mov.u32 %0, %%cluster_ctarank;" : "=r"(r)); return r;
}
__device__ __forceinline__ unsigned cvta_s(const void* p) {
    unsigned r;
    asm("{ .reg .u64 t; cvta.to.shared.u64 t, %1; cvt.u32.u64 %0, t; }"
        : "=r"(r) : "l"(p));
    return r;
}
__device__ __forceinline__ unsigned mapa_s(unsigned laddr, unsigned rank) {
    unsigned r;
    asm("mapa.shared::cluster.u32 %0, %1, %2;" : "=r"(r) : "r"(laddr), "r"(rank));
    return r;
}
__device__ __forceinline__ unsigned long long packf2(float lo, float hi) {
    unsigned long long r;
    asm("mov.b64 %0, {%1, %2};" : "=l"(r) : "f"(lo), "f"(hi));
    return r;
}
__device__ __forceinline__ void unpackf2(unsigned long long v, float& lo, float& hi) {
    asm("mov.b64 {%0, %1}, %2;" : "=f"(lo), "=f"(hi) : "l"(v));
}
__device__ __forceinline__ unsigned long long addx2(unsigned long long a,
                                                    unsigned long long b) {
    unsigned long long r;
    asm("add.rn.f32x2 %0, %1, %2;" : "=l"(r) : "l"(a), "l"(b));
    return r;
}
__device__ __forceinline__ unsigned long long mulx2(unsigned long long a,
                                                    unsigned long long b) {
    unsigned long long r;
    asm("mul.rn.f32x2 %0, %1, %2;" : "=l"(r) : "l"(a), "l"(b));
    return r;
}
__device__ __forceinline__ unsigned long long fmx2(unsigned long long a,
                                                   unsigned long long b,
                                                   unsigned long long c) {
    unsigned long long r;
    asm("fma.rn.f32x2 %0, %1, %2, %3;" : "=l"(r) : "l"(a), "l"(b), "l"(c));
    return r;
}
__device__ __forceinline__ void st_cluster_v4(unsigned raddr, unsigned a, unsigned b,
                                              unsigned c, unsigned d) {
    asm volatile("st.shared::cluster.v4.b32 [%0], {%1,%2,%3,%4};"
                 :: "r"(raddr), "r"(a), "r"(b), "r"(c), "r"(d) : "memory");
}
__device__ __forceinline__ void st_cluster_u32(unsigned raddr, unsigned v) {
    asm volatile("st.shared::cluster.u32 [%0], %1;" :: "r"(raddr), "r"(v) : "memory");
}
__device__ __forceinline__ void cluster_bar() {
    asm volatile("barrier.cluster.arrive.aligned;" ::: "memory");
    asm volatile("barrier.cluster.wait.aligned;"   ::: "memory");
}

__global__ void __launch_bounds__(TPB, 1)
fps_kernel(const float* __restrict__ xyz, float* __restrict__ out) {
    extern __shared__ __align__(16) unsigned char smem_raw[];
    Smem* s = reinterpret_cast<Smem*>(smem_raw);

    const int      tid  = threadIdx.x;
    const unsigned lane = tid & 31;
    const unsigned warp = (unsigned)tid >> 5;
    const unsigned rank = ctarank();
    const int      batch = blockIdx.x / CSIZE;

    const float* __restrict__ base = xyz + (size_t)batch * NPTS * 3;
    const unsigned pbase = rank * PPB;

    // ---- fill SMEM with ALL pairs (packed); keep first REGJ in registers ----
    unsigned long long X[REGJ], Y[REGJ], Z[REGJ];
#pragma unroll
    for (int j = 0; j < TOTJ; ++j) {
        unsigned P = (unsigned)j * TPB + (unsigned)tid;
        const float2* p = reinterpret_cast<const float2*>(
            base + (size_t)(pbase + 2u * P) * 3);
        float2 a = p[0];  // x0 y0
        float2 b = p[1];  // z0 x1
        float2 c = p[2];  // y1 z1
        unsigned long long px = packf2(a.x, b.y);
        unsigned long long py = packf2(a.y, c.x);
        unsigned long long pz = packf2(b.x, c.y);
        s->xs2[P] = px; s->ys2[P] = py; s->zs2[P] = pz;
        if (j < REGJ) { X[j] = px; Y[j] = py; Z[j] = pz; }
    }

    float m[NPT];
#pragma unroll
    for (int k = 0; k < NPT; ++k) m[k] = __int_as_float(0x7f800000);  // +inf

    // remote slot addresses for pushes (warp0 lanes < CSIZE), both parities
    unsigned rs0 = 0, rs1 = 0;
    if (warp == 0 && lane < CSIZE) {
        rs0 = mapa_s(cvta_s(&s->slots[0][rank]), lane);
        rs1 = mapa_s(cvta_s(&s->slots[1][rank]), lane);
    }

    // initial centroid = point 0 of this batch
    float cx = __ldg(base + 0);
    float cy = __ldg(base + 1);
    float cz = __ldg(base + 2);
    if (rank == 0 && tid == 0) {
        float* o = out + (size_t)batch * NSAMP * 3;
        o[0] = cx; o[1] = cy; o[2] = cz;
    }
    __syncthreads();   // smem mirror ready

    for (int t = 1; t < NSAMP; ++t) {
        const unsigned long long ncx = packf2(-cx, -cx);
        const unsigned long long ncy = packf2(-cy, -cy);
        const unsigned long long ncz = packf2(-cz, -cz);

        // ---- update mindist; two independent max chains ----
        float bmA = -1.0f, bmB = -1.0f;
#pragma unroll
        for (int j = 0; j < REGJ; ++j) {
            unsigned long long dx = addx2(X[j], ncx);
            unsigned long long dy = addx2(Y[j], ncy);
            unsigned long long dz = addx2(Z[j], ncz);
            unsigned long long dd = mulx2(dx, dx);
            dd = fmx2(dy, dy, dd);
            dd = fmx2(dz, dz, dd);
            float d0, d1; unpackf2(dd, d0, d1);
            float m0 = fminf(m[2 * j],     d0);
            float m1 = fminf(m[2 * j + 1], d1);
            m[2 * j] = m0; m[2 * j + 1] = m1;
            bmA = fmaxf(bmA, m0);
            bmB = fmaxf(bmB, m1);
        }
#pragma unroll
        for (int j = REGJ; j < TOTJ; ++j) {
            unsigned P = (unsigned)j * TPB + (unsigned)tid;
            unsigned long long dx = addx2(s->xs2[P], ncx);
            unsigned long long dy = addx2(s->ys2[P], ncy);
            unsigned long long dz = addx2(s->zs2[P], ncz);
            unsigned long long dd = mulx2(dx, dx);
            dd = fmx2(dy, dy, dd);
            dd = fmx2(dz, dz, dd);
            float d0, d1; unpackf2(dd, d0, d1);
            float m0 = fminf(m[2 * j],     d0);
            float m1 = fminf(m[2 * j + 1], d1);
            m[2 * j] = m0; m[2 * j + 1] = m1;
            bmA = fmaxf(bmA, m0);
            bmB = fmaxf(bmB, m1);
        }
        const float bm = fmaxf(bmA, bmB);

        // ---- smallest k with m[k]==bm (downward scan) ----
        int kk = 0;
#pragma unroll
        for (int k = NPT - 1; k >= 0; --k)
            if (m[k] == bm) kk = k;

        unsigned Pw   = (unsigned)(kk >> 1) * TPB + (unsigned)tid;
        unsigned gidx = pbase + 2u * Pw + (unsigned)(kk & 1);
        float a0, a1, b0, b1, c0, c1;
        unpackf2(s->xs2[Pw], a0, a1);
        unpackf2(s->ys2[Pw], b0, b1);
        unpackf2(s->zs2[Pw], c0, c1);
        float candx = (kk & 1) ? a1 : a0;
        float candy = (kk & 1) ? b1 : b0;
        float candz = (kk & 1) ? c1 : c0;

        // ---- warp reduce: max dist bits, then min index among maxima ----
        unsigned vb = __float_as_uint(bm);   // d>=0: int order == float order
        unsigned wv = __reduce_max_sync(0xffffffffu, vb);
        unsigned cd = (vb == wv) ? gidx : 0xffffffffu;
        unsigned wi = __reduce_min_sync(0xffffffffu, cd);
        if (cd == wi) {                      // unique winner lane stores
            *reinterpret_cast<uint4*>(&s->warpred[warp]) =
                make_uint4(wv, wi, __float_as_uint(candx), __float_as_uint(candy));
            s->warpred[warp].z = candz;
        }
        __syncthreads();

        const int par = t & 1;

        // ---- block reduce over 32 warp partials + push to all 8 peers ----
        if (warp == 0) {
            uint4 w = *reinterpret_cast<const uint4*>(&s->warpred[lane]);  // 32 lanes, 32 warps
            unsigned v = w.x, i = w.y, xb = w.z, yb = w.w;
            unsigned zb = __float_as_uint(s->warpred[lane].z);
            unsigned bv = __reduce_max_sync(0xffffffffu, v);
            unsigned bc = (v == bv) ? i : 0xffffffffu;
            unsigned bi = __reduce_min_sync(0xffffffffu, bc);
            unsigned msk = __ballot_sync(0xffffffffu, bc == bi);
            int L = __ffs(msk) - 1;
            xb = __shfl_sync(0xffffffffu, xb, L);
            yb = __shfl_sync(0xffffffffu, yb, L);
            zb = __shfl_sync(0xffffffffu, zb, L);
            if (lane < CSIZE) {
                unsigned ra = par ? rs1 : rs0;
                st_cluster_v4(ra, bv, bi, xb, yb);
                st_cluster_u32(ra + 16, zb);
            }
        }

        // one cluster barrier per step (arrive releases the DSMEM stores)
        cluster_bar();

        // ---- EVERY warp reduces the 8 slots -> next centroid in registers ----
        {
            unsigned v = 0, i = 0xffffffffu, xb = 0, yb = 0, zb = 0;
            if (lane < CSIZE) {
                uint4 w = *reinterpret_cast<const uint4*>(&s->slots[par][lane]);
                v = w.x; i = w.y; xb = w.z; yb = w.w;
                zb = __float_as_uint(s->slots[par][lane].z);
            }
            unsigned cv = __reduce_max_sync(0xffffffffu, v);
            unsigned cc = (v == cv) ? i : 0xffffffffu;
            unsigned ci = __reduce_min_sync(0xffffffffu, cc);
            unsigned msk = __ballot_sync(0xffffffffu, cc == ci);
            int W = __ffs(msk) - 1;
            cx = __uint_as_float(__shfl_sync(0xffffffffu, xb, W));
            cy = __uint_as_float(__shfl_sync(0xffffffffu, yb, W));
            cz = __uint_as_float(__shfl_sync(0xffffffffu, zb, W));
            if (rank == 0 && tid == 0) {
                float* o = out + ((size_t)batch * NSAMP + (size_t)t) * 3;
                o[0] = cx; o[1] = cy; o[2] = cz;
            }
        }
        // warpred: each warp rewrites only its own entry after its own warp
        // stage; warp0 reads right after the block-wide __syncthreads.
        // slots: double-buffered by parity, protected by the cluster barrier.
    }

    cluster_bar();  // keep CTAs alive until all DSMEM traffic has landed
}

extern "C" void kernel_launch(void* const* d_in, const int* in_sizes, int n_in,
                              void* d_out, int out_size) {
    (void)in_sizes; (void)n_in; (void)out_size;
    const float* xyz = (const float*)d_in[0];
    float* out = (float*)d_out;

    cudaFuncSetAttribute(fps_kernel,
                         cudaFuncAttributeMaxDynamicSharedMemorySize,
                         (int)sizeof(Smem));

    cudaLaunchConfig_t cfg = {};
    cfg.gridDim  = dim3(NB * CSIZE, 1, 1);   // 64 CTAs
    cfg.blockDim = dim3(TPB, 1, 1);
    cfg.dynamicSmemBytes = sizeof(Smem);
    cfg.stream = 0;

    cudaLaunchAttribute attr[1];
    attr[0].id = cudaLaunchAttributeClusterDimension;
    attr[0].val.clusterDim.x = CSIZE;
    attr[0].val.clusterDim.y = 1;
    attr[0].val.clusterDim.z = 1;
    cfg.attrs = attr;
    cfg.numAttrs = 1;

    cudaLaunchKernelEx(&cfg, fps_kernel, xyz, out);
}